// round 6
// baseline (speedup 1.0000x reference)
#include <cuda_runtime.h>
#include <cuda_bf16.h>
#include <cstdint>

// ---------------------------------------------------------------------------
// LSTM cell: h_new = tanh(c*sigm(zf) + sigm(zi)*tanh(zp)) * sigm(zs)
// z_g = [x,h] @ W_g + b_g     B=4096, IN=H=1024, K=2048
//
// Harness PTX target is compute_100 (no 'a') => tcgen05 unavailable.
// mma.sync.m16n8k8.tf32, rna-prerounded operands, cp.async 4-stage pipeline,
// XOR-swizzled smem, ldmatrix.x4 fragment loads (register double-buffered),
// gate-interleaved weight layout so the LSTM epilogue fuses into the GEMM.
// ---------------------------------------------------------------------------

#define B_DIM 4096
#define H_DIM 1024
#define K_DIM 2048
#define N_ALL 4096          // 4 gates x 1024

__device__ float g_hx[(size_t)B_DIM * K_DIM];          // 32 MB  [b][k] tf32
// gate-interleaved: row ng' = (n>>5)*128 + ((n>>3)&3)*32 + gate*8 + (n&7)
__device__ float g_wt[(size_t)N_ALL * K_DIM];          // 32 MB  [ng'][k] tf32

__device__ __forceinline__ float to_tf32(float x) {
    uint32_t u;
    asm("cvt.rna.tf32.f32 %0, %1;" : "=r"(u) : "f"(x));
    return __uint_as_float(u);
}

__device__ __forceinline__ uint32_t swz(uint32_t off) {   // byte-offset XOR swizzle
    return off ^ ((off >> 3) & 0x70);
}

__device__ __forceinline__ void cp16(uint32_t dst_smem, const void* src) {
    asm volatile("cp.async.cg.shared.global [%0], [%1], 16;"
                 :: "r"(dst_smem), "l"(src));
}

__device__ __forceinline__ uint32_t smem_u32(const void* p) {
    uint32_t a;
    asm("{ .reg .u64 t; cvta.to.shared.u64 t, %1; cvt.u32.u64 %0, t; }"
        : "=r"(a) : "l"(p));
    return a;
}

__device__ __forceinline__ void mma_tf32(float* d, const uint32_t* a, const uint32_t* b) {
    asm volatile(
        "mma.sync.aligned.m16n8k8.row.col.f32.tf32.tf32.f32 "
        "{%0,%1,%2,%3}, {%4,%5,%6,%7}, {%8,%9}, {%0,%1,%2,%3};"
        : "+f"(d[0]), "+f"(d[1]), "+f"(d[2]), "+f"(d[3])
        : "r"(a[0]), "r"(a[1]), "r"(a[2]), "r"(a[3]), "r"(b[0]), "r"(b[1]));
}

__device__ __forceinline__ void ldsm_x4(uint32_t* r, uint32_t addr) {
    asm volatile(
        "ldmatrix.sync.aligned.m8n8.x4.shared.b16 {%0,%1,%2,%3}, [%4];"
        : "=r"(r[0]), "=r"(r[1]), "=r"(r[2]), "=r"(r[3]) : "r"(addr));
}

// ---------------------------------------------------------------------------
// prep 1: g_hx[b][k] = rna_tf32( k<1024 ? x[b][k] : h[b][k-1024] )
// ---------------------------------------------------------------------------
__global__ void prep_hx(const float4* __restrict__ x, const float4* __restrict__ h) {
    int v = blockIdx.x * 256 + threadIdx.x;          // 2,097,152 float4s
    int b = v >> 9;                                   // 512 float4 per row
    int kk = v & 511;
    float4 t = (kk < 256) ? x[(size_t)b * 256 + kk]
                          : h[(size_t)b * 256 + (kk - 256)];
    t.x = to_tf32(t.x); t.y = to_tf32(t.y); t.z = to_tf32(t.z); t.w = to_tf32(t.w);
    reinterpret_cast<float4*>(g_hx)[v] = t;
}

// ---------------------------------------------------------------------------
// prep 2: gate-interleaved transpose:
//   g_wt[nb*128 + (r>>3)*32 + gate*8 + (r&7)][k] = rna_tf32(W_gate[k][nb*32+r])
// ---------------------------------------------------------------------------
__global__ void prep_wt(const float* __restrict__ Wf, const float* __restrict__ Wi,
                        const float* __restrict__ Ws, const float* __restrict__ Wp) {
    __shared__ float tile[32][33];
    int z = blockIdx.z;
    const float* W = (z == 0) ? Wf : (z == 1) ? Wi : (z == 2) ? Ws : Wp;
    int nb = blockIdx.x;                 // n block of 32
    int n0 = nb * 32, k0 = blockIdx.y * 32;
    int tx = threadIdx.x, ty = threadIdx.y;
    #pragma unroll
    for (int r = ty; r < 32; r += 8)
        tile[r][tx] = to_tf32(W[(size_t)(k0 + r) * H_DIM + n0 + tx]);
    __syncthreads();
    #pragma unroll
    for (int r = ty; r < 32; r += 8) {
        int ngp = nb * 128 + (r >> 3) * 32 + z * 8 + (r & 7);
        g_wt[(size_t)ngp * K_DIM + k0 + tx] = tile[tx][r];
    }
}

// ---------------------------------------------------------------------------
// Fused GEMM + LSTM epilogue.
//   CTA 128(m) x 128(col) where 128 cols = 32 n-values x 4 gates (nt = gate).
//   BK=32, 4 cp.async stages, 256 threads, warp grid 2(m) x 4(n-sub),
//   warp tile 64x32, ldmatrix.x4, register double-buffered fragments.
// ---------------------------------------------------------------------------
#define BK 32
#define STAGES 4
#define STAGE_FLOATS 8192            // 32KB / 4
#define B_OFF 4096                   // floats

__global__ void __launch_bounds__(256, 1)
gemm_lstm(const float* __restrict__ cin,
          const float* __restrict__ bfo, const float* __restrict__ big,
          const float* __restrict__ bse, const float* __restrict__ bpr,
          float* __restrict__ out) {
    extern __shared__ float smem[];
    __shared__ float sbias[128];                 // [gate*32 + n5]
    const uint32_t sbase = smem_u32(smem);
    const int tid = threadIdx.x;
    const int wid = tid >> 5, lane = tid & 31;
    const int wm = wid & 1;          // 0..1
    const int wn = wid >> 1;         // 0..3  (n sub-block of 8)
    const int qr = lane >> 2, qc = lane & 3;
    const int m0 = blockIdx.y * 128;
    const int nb = blockIdx.x;                   // n block of 32

    if (tid < 128) {
        const float* bp_[4] = {bfo, big, bse, bpr};
        sbias[tid] = bp_[tid >> 5][nb * 32 + (tid & 31)];
    }

    const float* Abase = g_hx + (size_t)m0 * K_DIM;
    const float* Bbase = g_wt + (size_t)(nb * 128) * K_DIM;

    uint32_t dsw[4];
    uint32_t srcoff[4];
    #pragma unroll
    for (int j = 0; j < 4; j++) {
        int g = tid + 256 * j;       // 0..1023
        int row = g >> 3;            // 0..127
        int gc = g & 7;              // 16B granule in 128B row
        dsw[j] = swz((uint32_t)(row * 128 + gc * 16));
        srcoff[j] = (uint32_t)(row * K_DIM + gc * 4);
    }

    auto load_stage = [&](int s, int kt) {
        const uint32_t st = sbase + (uint32_t)s * (STAGE_FLOATS * 4);
        const float* ak = Abase + kt * BK;
        const float* bk = Bbase + kt * BK;
        #pragma unroll
        for (int j = 0; j < 4; j++) {
            cp16(st + dsw[j], ak + srcoff[j]);
            cp16(st + B_OFF * 4 + dsw[j], bk + srcoff[j]);
        }
        asm volatile("cp.async.commit_group;" ::: "memory");
    };

    load_stage(0, 0);
    load_stage(1, 1);
    load_stage(2, 2);

    float acc[4][4][4];
    #pragma unroll
    for (int i = 0; i < 4; i++)
        #pragma unroll
        for (int j = 0; j < 4; j++)
            #pragma unroll
            for (int v = 0; v < 4; v++) acc[i][j][v] = 0.0f;

    // ldmatrix lane-invariant base offsets
    const uint32_t a_row = (uint32_t)(wm * 64 + (lane & 15));
    const uint32_t a_col = (lane & 16) ? 16u : 0u;
    const uint32_t a_off0 = a_row * 128 + a_col;
    const uint32_t b_n = (uint32_t)(wn * 32 + ((lane & 16) ? 8 : 0) + (lane & 7));
    const uint32_t b_col = (lane & 8) ? 16u : 0u;
    const uint32_t b_off0 = b_n * 128 + b_col;

    uint32_t fa[2][4][4], fb[2][4][2];

    auto load_frags = [&](int buf, uint32_t stA, uint32_t stB, uint32_t kb) {
        #pragma unroll
        for (int mt = 0; mt < 4; mt++)
            ldsm_x4(fa[buf][mt], stA + swz(a_off0 + (uint32_t)mt * 2048 + kb));
        uint32_t t0[4], t1[4];
        ldsm_x4(t0, stB + swz(b_off0 + kb));
        ldsm_x4(t1, stB + swz(b_off0 + 2048 + kb));   // +16 col-rows
        fb[buf][0][0] = t0[0]; fb[buf][0][1] = t0[1];
        fb[buf][1][0] = t0[2]; fb[buf][1][1] = t0[3];
        fb[buf][2][0] = t1[0]; fb[buf][2][1] = t1[1];
        fb[buf][3][0] = t1[2]; fb[buf][3][1] = t1[3];
    };

    const int KT = K_DIM / BK;       // 64
    for (int kt = 0; kt < KT; kt++) {
        asm volatile("cp.async.wait_group 2;" ::: "memory");
        __syncthreads();

        const int s = kt & (STAGES - 1);
        const uint32_t stA = sbase + (uint32_t)s * (STAGE_FLOATS * 4);
        const uint32_t stB = stA + B_OFF * 4;

        load_frags(0, stA, stB, 0);
        #pragma unroll
        for (int kk = 0; kk < BK; kk += 8) {
            const int cur = (kk >> 3) & 1;
            if (kk + 8 < BK)
                load_frags(cur ^ 1, stA, stB, (uint32_t)(kk + 8) * 4);
            #pragma unroll
            for (int mt = 0; mt < 4; mt++)
                #pragma unroll
                for (int nt = 0; nt < 4; nt++)
                    mma_tf32(acc[mt][nt], fa[cur][mt], fb[cur][nt]);
        }

        if (kt + STAGES - 1 < KT) {
            load_stage((kt + STAGES - 1) & (STAGES - 1), kt + STAGES - 1);
        } else {
            asm volatile("cp.async.commit_group;" ::: "memory");
        }
    }

    // ---------------- fused LSTM epilogue ----------------
    // thread covers rows m0+wm*64+mt*16+{qr,qr+8}, n = nb*32 + wn*8 + qc*2 +{0,1}
    // acc[mt][gate][half*2+e]
    const int n5 = wn * 8 + qc * 2;              // 0..30 within n-block
    const int ng = nb * 32 + n5;                 // global n
    float bsv[4][2];
    #pragma unroll
    for (int g = 0; g < 4; g++) {
        bsv[g][0] = sbias[g * 32 + n5];
        bsv[g][1] = sbias[g * 32 + n5 + 1];
    }
    #pragma unroll
    for (int mt = 0; mt < 4; mt++) {
        const int row0 = m0 + wm * 64 + mt * 16 + qr;
        #pragma unroll
        for (int half = 0; half < 2; half++) {
            const int row = row0 + half * 8;
            const float2 cc = *reinterpret_cast<const float2*>(
                cin + (size_t)row * H_DIM + ng);
            float res[2];
            #pragma unroll
            for (int e = 0; e < 2; e++) {
                const int v = half * 2 + e;
                float zf = acc[mt][0][v] + bsv[0][e];
                float zi = acc[mt][1][v] + bsv[1][e];
                float zs = acc[mt][2][v] + bsv[2][e];
                float zp = acc[mt][3][v] + bsv[3][e];
                float f  = 1.0f / (1.0f + __expf(-zf));
                float ig = 1.0f / (1.0f + __expf(-zi));
                float sl = 1.0f / (1.0f + __expf(-zs));
                float pr = 1.0f - 2.0f / (1.0f + __expf(2.0f * zp));
                float ca = (e == 0) ? cc.x : cc.y;
                float cn = ca * f + ig * pr;
                float th = 1.0f - 2.0f / (1.0f + __expf(2.0f * cn));
                res[e] = th * sl;
            }
            *reinterpret_cast<float2*>(out + (size_t)row * H_DIM + ng) =
                make_float2(res[0], res[1]);
        }
    }
}

// ---------------------------------------------------------------------------
// launch
// ---------------------------------------------------------------------------
extern "C" void kernel_launch(void* const* d_in, const int* in_sizes, int n_in,
                              void* d_out, int out_size) {
    const float* x  = (const float*)d_in[0];
    const float* h  = (const float*)d_in[1];
    const float* c  = (const float*)d_in[2];
    const float* Wf = (const float*)d_in[3];
    const float* bf = (const float*)d_in[4];
    const float* Wi = (const float*)d_in[5];
    const float* bi = (const float*)d_in[6];
    const float* Ws = (const float*)d_in[7];
    const float* bs = (const float*)d_in[8];
    const float* Wp = (const float*)d_in[9];
    const float* bp = (const float*)d_in[10];
    float* out = (float*)d_out;

    prep_hx<<<8192, 256>>>((const float4*)x, (const float4*)h);
    prep_wt<<<dim3(32, 64, 4), dim3(32, 8)>>>(Wf, Wi, Ws, Wp);

    cudaFuncSetAttribute(gemm_lstm, cudaFuncAttributeMaxDynamicSharedMemorySize,
                         STAGES * STAGE_FLOATS * 4);
    gemm_lstm<<<dim3(32, 32), 256, STAGES * STAGE_FLOATS * 4>>>(
        c, bf, bi, bs, bp, out);
}